// round 13
// baseline (speedup 1.0000x reference)
#include <cuda_runtime.h>
#include <cuda_fp16.h>
#include <cstdint>

// Fixed shapes: B=8, H=W=128, C=256, heads=8, hd=32, ws=8
#define NTOK  131072

// device-global scratch (allocation-free rule)
__device__ __half g_Wh[4 * 256 * 256];        // fp16 weights: q,k,v,p
__device__ float  g_Wt[2][256][256];          // fp32 transposed Wq, Wk (k-major) for prep
__device__ __half g_tabh[3][64][256];         // fp16: pe@Wq^T+bq, pe@Wk^T+bk, bv

// ---------------------------------------------------------------------------
// helpers
// ---------------------------------------------------------------------------
__device__ __forceinline__ void mma_f16(float& c0, float& c1, float& c2, float& c3,
                                        uint32_t a0, uint32_t a1, uint32_t a2, uint32_t a3,
                                        uint32_t b0, uint32_t b1) {
    asm volatile(
        "mma.sync.aligned.m16n8k16.row.col.f32.f16.f16.f32 "
        "{%0,%1,%2,%3}, {%4,%5,%6,%7}, {%8,%9}, {%0,%1,%2,%3};\n"
        : "+f"(c0), "+f"(c1), "+f"(c2), "+f"(c3)
        : "r"(a0), "r"(a1), "r"(a2), "r"(a3), "r"(b0), "r"(b1));
}

__device__ __forceinline__ void ldsm4(uint32_t& r0, uint32_t& r1, uint32_t& r2, uint32_t& r3,
                                      uint32_t addr) {
    asm volatile("ldmatrix.sync.aligned.m8n8.x4.shared.b16 {%0,%1,%2,%3}, [%4];"
                 : "=r"(r0), "=r"(r1), "=r"(r2), "=r"(r3) : "r"(addr));
}

__device__ __forceinline__ void ldsm4t(uint32_t& r0, uint32_t& r1, uint32_t& r2, uint32_t& r3,
                                       uint32_t addr) {
    asm volatile("ldmatrix.sync.aligned.m8n8.x4.trans.shared.b16 {%0,%1,%2,%3}, [%4];"
                 : "=r"(r0), "=r"(r1), "=r"(r2), "=r"(r3) : "r"(addr));
}

__device__ __forceinline__ uint32_t smem_u32(const void* p) {
    uint32_t a;
    asm("{ .reg .u64 t; cvta.to.shared.u64 t, %1; cvt.u32.u64 %0, t; }" : "=r"(a) : "l"(p));
    return a;
}

__device__ __forceinline__ uint32_t pack_h2(float lo, float hi) {
    __half2 h = __floats2half2_rn(lo, hi);
    return *(uint32_t*)&h;
}

__device__ __forceinline__ void cp16(uint32_t smem, const void* gmem) {
    asm volatile("cp.async.cg.shared.global [%0], [%1], 16;" :: "r"(smem), "l"(gmem));
}

// ---------------------------------------------------------------------------
// w2h: fp32 -> fp16 weights [q,k,v,p]; also fp32 transposed Wq/Wk for prep
// ---------------------------------------------------------------------------
__global__ void w2h_kernel(const float* __restrict__ Wq, const float* __restrict__ Wk,
                           const float* __restrict__ Wv, const float* __restrict__ Wp) {
    int gid = blockIdx.x * 256 + threadIdx.x;       // 0..65535
    int mat = gid >> 14;
    int off = (gid & 16383) << 2;
    const float* W = (mat == 0) ? Wq : (mat == 1) ? Wk : (mat == 2) ? Wv : Wp;
    float4 v = *(const float4*)(W + off);
    __half2 h0 = __floats2half2_rn(v.x, v.y);
    __half2 h1 = __floats2half2_rn(v.z, v.w);
    *(uint2*)(g_Wh + (size_t)mat * 65536 + off) = make_uint2(*(uint32_t*)&h0, *(uint32_t*)&h1);
    if (mat < 2) {                                  // transpose for prep (k-major)
        int r = off >> 8;                           // output-channel row n
        int c = off & 255;                          // k column
        g_Wt[mat][c + 0][r] = v.x;
        g_Wt[mat][c + 1][r] = v.y;
        g_Wt[mat][c + 2][r] = v.z;
        g_Wt[mat][c + 3][r] = v.w;
    }
}

// ---------------------------------------------------------------------------
// prep: g_tabh[0] = pe@Wq^T+bq, [1] = pe@Wk^T+bk, [2] = bv  (fp16)
// Reads transposed weights -> coalesced (thread = n, loop = k).
// ---------------------------------------------------------------------------
__global__ void prep_kernel(const float* __restrict__ bq, const float* __restrict__ bk,
                            const float* __restrict__ bv) {
    __shared__ float per[256];
    int p = blockIdx.x, n = threadIdx.x;
    int wy = p >> 3, wx = p & 7;
    {
        int f = n & 63, quad = n >> 6;
        float coord = (quad < 2) ? (float)wx : (float)wy;
        float arg = 3.14f * coord * (float)f * (1.0f / 200.0f);
        per[n] = (quad & 1) ? cosf(arg) : sinf(arg);
    }
    __syncthreads();
    float sq = bq[n], sk = bk[n];
#pragma unroll 8
    for (int k = 0; k < 256; k++) {
        float pv = per[k];
        sq = fmaf(pv, g_Wt[0][k][n], sq);
        sk = fmaf(pv, g_Wt[1][k][n], sk);
    }
    g_tabh[0][p][n] = __float2half_rn(sq);
    g_tabh[1][p][n] = __float2half_rn(sk);
    g_tabh[2][p][n] = __float2half_rn(bv[n]);
}

// ---------------------------------------------------------------------------
// Fused kernel: one block per window (64 tokens), 512 threads / 16 warps.
// warp = (mi = warp&1 -> 32 query rows, hn = warp>>1 -> head / 32-col slice).
// Phases: stage x -> GEMM K -> GEMM V -> GEMM Q (regs) -> [issue Wp chunk0]
// -> attention -> O to smem -> GEMM proj (chunk0 already in flight) -> out.
// Weights stream via cp.async (L2-resident).
// ---------------------------------------------------------------------------
#define AHS 264                   // halves; row stride of As/Ks/Vs
#define BHS 72                    // halves; weight-chunk row stride
#define OFF_K  33792u             // 64*264*2
#define OFF_V  67584u
#define OFF_B  101376u            // + 64*264*2
#define SMEM_BYTES 175104u        // + 2*256*72*2

__global__ void __launch_bounds__(512, 1) fused_kernel(
        const float* __restrict__ x, const __half* __restrict__ Wh,
        const float* __restrict__ bp, float* __restrict__ out) {
    extern __shared__ char smc[];
    __half* As = (__half*)smc;            // x tile, later O tile
    uint32_t smb = smem_u32(smc);

    int tid = threadIdx.x, lane = tid & 31, warp = tid >> 5;
    int mi = warp & 1, hn = warp >> 1;
    int lr = lane & 15, lc8 = (lane >> 4) << 3;
    int lq = lane >> 2, kb2 = (lane & 3) << 1;

    int win = blockIdx.x;
    int bi = win >> 8, wl = win & 255;
    int wyi = wl >> 4, wxi = wl & 15;
    long base = (long)bi * 16384 + (wyi * 8) * 128 + wxi * 8;   // + (t>>3)*128 + (t&7)

    // ---- stage x window tile (64 x 256 fp32 -> fp16 smem) ----
#pragma unroll
    for (int i = 0; i < 8; i++) {
        int f = tid + i * 512;            // 0..4095
        int t = f >> 6;
        int c4 = (f & 63) << 2;
        long gr = base + (t >> 3) * 128 + (t & 7);
        float4 v = *(const float4*)(x + gr * 256 + c4);
        __half2 h0 = __floats2half2_rn(v.x, v.y);
        __half2 h1 = __floats2half2_rn(v.z, v.w);
        *(uint2*)(As + t * AHS + c4) = make_uint2(*(uint32_t*)&h0, *(uint32_t*)&h1);
    }

    // helper: issue one k64 weight chunk (256 rows x 64 halves) into a buffer
    auto issue_chunk = [&](const __half* src, int buf) {
#pragma unroll
        for (int i = 0; i < 4; i++) {
            int f = tid + i * 512;        // 0..2047
            int row = f >> 3, seg = f & 7;
            cp16(smb + OFF_B + (uint32_t)(buf * 256 * BHS + row * BHS + seg * 8) * 2,
                 src + (size_t)row * 256 + seg * 8);
        }
        asm volatile("cp.async.commit_group;");
    };

    // ---- shared GEMM mainloop: acc[mf][ni] = A[rows mi*32..] @ Wm[cols hn*32..]^T
    // PRELOADED=false: issues chunk 0 itself.  true: chunk 0 already in flight (buf 0).
    auto run_gemm = [&](const __half* Wm, bool preloaded, float (&acc)[2][4][4]) {
#pragma unroll
        for (int a = 0; a < 2; a++)
#pragma unroll
            for (int b = 0; b < 4; b++)
#pragma unroll
                for (int r = 0; r < 4; r++) acc[a][b][r] = 0.f;
        if (!preloaded) issue_chunk(Wm, 0);
        asm volatile("cp.async.wait_group 0;");
        __syncthreads();

        for (int c = 0; c < 4; c++) {
            int buf = c & 1;
            if (c < 3) issue_chunk(Wm + (c + 1) * 64, buf ^ 1);
            uint32_t bB = smb + OFF_B + (uint32_t)buf * (256 * BHS * 2);
#pragma unroll
            for (int kt = 0; kt < 4; kt++) {
                int kcol = c * 64 + kt * 16 + lc8;
                uint32_t af[2][4];
#pragma unroll
                for (int mf = 0; mf < 2; mf++)
                    ldsm4(af[mf][0], af[mf][1], af[mf][2], af[mf][3],
                          smb + (uint32_t)(((mi * 32 + mf * 16 + lr) * AHS + kcol) * 2));
                uint32_t bf[4][2];
#pragma unroll
                for (int ntp = 0; ntp < 2; ntp++) {
                    uint32_t r0, r1, r2, r3;
                    ldsm4(r0, r1, r2, r3,
                          bB + (uint32_t)(((hn * 32 + ntp * 16 + lr) * BHS + kt * 16 + lc8) * 2));
                    bf[ntp * 2][0] = r0; bf[ntp * 2][1] = r2;
                    bf[ntp * 2 + 1][0] = r1; bf[ntp * 2 + 1][1] = r3;
                }
#pragma unroll
                for (int mf = 0; mf < 2; mf++)
#pragma unroll
                    for (int ni = 0; ni < 4; ni++)
                        mma_f16(acc[mf][ni][0], acc[mf][ni][1], acc[mf][ni][2], acc[mf][ni][3],
                                af[mf][0], af[mf][1], af[mf][2], af[mf][3],
                                bf[ni][0], bf[ni][1]);
            }
            if (c < 3) {                  // c==3: no barrier needed; the next phase's
                asm volatile("cp.async.wait_group 0;");   // entry sync orders smem reuse
                __syncthreads();
            }
        }
    };

    // C-frag + fp16 table -> smem (used for K and V)
    auto store_kv = [&](float (&acc)[2][4][4], const __half* tab, uint32_t dstOff) {
#pragma unroll
        for (int mf = 0; mf < 2; mf++) {
            int r = mi * 32 + mf * 16 + lq;
#pragma unroll
            for (int ni = 0; ni < 4; ni++) {
                int cb = hn * 32 + ni * 8 + kb2;
                float2 t0 = __half22float2(*(const __half2*)&tab[r * 256 + cb]);
                float2 t1 = __half22float2(*(const __half2*)&tab[(r + 8) * 256 + cb]);
                *(uint32_t*)(smc + dstOff + (uint32_t)((r * AHS + cb) * 2)) =
                    pack_h2(acc[mf][ni][0] + t0.x, acc[mf][ni][1] + t0.y);
                *(uint32_t*)(smc + dstOff + (uint32_t)(((r + 8) * AHS + cb) * 2)) =
                    pack_h2(acc[mf][ni][2] + t1.x, acc[mf][ni][3] + t1.y);
            }
        }
    };

    float acc[2][4][4];

    // ---- K, V ----
    run_gemm(Wh + 65536, false, acc);              // Wk
    store_kv(acc, &g_tabh[1][0][0], OFF_K);
    run_gemm(Wh + 131072, false, acc);             // Wv
    store_kv(acc, &g_tabh[2][0][0], OFF_V);

    // ---- Q (stays in registers as mma A-frags, scale folded) ----
    run_gemm(Wh, false, acc);                      // Wq
    uint32_t afQ[2][2][4];
    {
        const __half* tq = &g_tabh[0][0][0];
        const float s = 0.17677669529663687f;      // 1/sqrt(32)
#pragma unroll
        for (int mf = 0; mf < 2; mf++) {
            int r = mi * 32 + mf * 16 + lq;
#pragma unroll
            for (int kf = 0; kf < 2; kf++) {
#pragma unroll
                for (int h = 0; h < 2; h++) {
                    int ni = 2 * kf + h;
                    int cb = hn * 32 + ni * 8 + kb2;
                    float2 t0 = __half22float2(*(const __half2*)&tq[r * 256 + cb]);
                    float2 t1 = __half22float2(*(const __half2*)&tq[(r + 8) * 256 + cb]);
                    afQ[mf][kf][2 * h] =
                        pack_h2((acc[mf][ni][0] + t0.x) * s, (acc[mf][ni][1] + t0.y) * s);
                    afQ[mf][kf][2 * h + 1] =
                        pack_h2((acc[mf][ni][2] + t1.x) * s, (acc[mf][ni][3] + t1.y) * s);
                }
            }
        }
    }

    // ---- issue Wp chunk 0 now: it loads during the whole attention phase.
    // buf 0 hazard-free: its last readers were in Q GEMM chunk 2 (c=2 barrier).
    issue_chunk(Wh + 196608, 0);

    // ---- S = Q K^T (32 rows x 64 keys per warp) ----
    float sc[2][8][4];
#pragma unroll
    for (int mf = 0; mf < 2; mf++)
#pragma unroll
        for (int nf = 0; nf < 8; nf++)
#pragma unroll
            for (int r = 0; r < 4; r++) sc[mf][nf][r] = 0.f;

#pragma unroll
    for (int kt = 0; kt < 2; kt++) {
#pragma unroll
        for (int nt = 0; nt < 4; nt++) {
            uint32_t b0, b1, b2, b3;
            ldsm4(b0, b1, b2, b3,
                  smb + OFF_K + (uint32_t)(((nt * 16 + lr) * AHS + hn * 32 + kt * 16 + lc8) * 2));
#pragma unroll
            for (int mf = 0; mf < 2; mf++) {
                mma_f16(sc[mf][nt * 2][0], sc[mf][nt * 2][1], sc[mf][nt * 2][2], sc[mf][nt * 2][3],
                        afQ[mf][kt][0], afQ[mf][kt][1], afQ[mf][kt][2], afQ[mf][kt][3], b0, b2);
                mma_f16(sc[mf][nt * 2 + 1][0], sc[mf][nt * 2 + 1][1],
                        sc[mf][nt * 2 + 1][2], sc[mf][nt * 2 + 1][3],
                        afQ[mf][kt][0], afQ[mf][kt][1], afQ[mf][kt][2], afQ[mf][kt][3], b1, b3);
            }
        }
    }

    // ---- softmax + P pack (scale already folded into Q) ----
    uint32_t pa[2][4][4];
#pragma unroll
    for (int mf = 0; mf < 2; mf++) {
        float m0 = -1e30f, m1 = -1e30f;
#pragma unroll
        for (int nf = 0; nf < 8; nf++) {
            m0 = fmaxf(m0, fmaxf(sc[mf][nf][0], sc[mf][nf][1]));
            m1 = fmaxf(m1, fmaxf(sc[mf][nf][2], sc[mf][nf][3]));
        }
        m0 = fmaxf(m0, __shfl_xor_sync(0xffffffffu, m0, 1));
        m0 = fmaxf(m0, __shfl_xor_sync(0xffffffffu, m0, 2));
        m1 = fmaxf(m1, __shfl_xor_sync(0xffffffffu, m1, 1));
        m1 = fmaxf(m1, __shfl_xor_sync(0xffffffffu, m1, 2));
        float s0 = 0.f, s1 = 0.f;
#pragma unroll
        for (int nf = 0; nf < 8; nf++) {
            sc[mf][nf][0] = __expf(sc[mf][nf][0] - m0);
            sc[mf][nf][1] = __expf(sc[mf][nf][1] - m0);
            sc[mf][nf][2] = __expf(sc[mf][nf][2] - m1);
            sc[mf][nf][3] = __expf(sc[mf][nf][3] - m1);
            s0 += sc[mf][nf][0] + sc[mf][nf][1];
            s1 += sc[mf][nf][2] + sc[mf][nf][3];
        }
        s0 += __shfl_xor_sync(0xffffffffu, s0, 1);
        s0 += __shfl_xor_sync(0xffffffffu, s0, 2);
        s1 += __shfl_xor_sync(0xffffffffu, s1, 1);
        s1 += __shfl_xor_sync(0xffffffffu, s1, 2);
        float inv0 = 1.0f / s0, inv1 = 1.0f / s1;
#pragma unroll
        for (int kf = 0; kf < 4; kf++) {
            pa[mf][kf][0] = pack_h2(sc[mf][2 * kf][0] * inv0, sc[mf][2 * kf][1] * inv0);
            pa[mf][kf][1] = pack_h2(sc[mf][2 * kf][2] * inv1, sc[mf][2 * kf][3] * inv1);
            pa[mf][kf][2] = pack_h2(sc[mf][2 * kf + 1][0] * inv0, sc[mf][2 * kf + 1][1] * inv0);
            pa[mf][kf][3] = pack_h2(sc[mf][2 * kf + 1][2] * inv1, sc[mf][2 * kf + 1][3] * inv1);
        }
    }

    // ---- O = P V ----
    float oc[2][4][4];
#pragma unroll
    for (int mf = 0; mf < 2; mf++)
#pragma unroll
        for (int nf = 0; nf < 4; nf++)
#pragma unroll
            for (int r = 0; r < 4; r++) oc[mf][nf][r] = 0.f;

#pragma unroll
    for (int kf = 0; kf < 4; kf++) {
#pragma unroll
        for (int tt = 0; tt < 2; tt++) {
            uint32_t b0, b1, b2, b3;
            ldsm4t(b0, b1, b2, b3,
                   smb + OFF_V + (uint32_t)(((kf * 16 + lr) * AHS + hn * 32 + tt * 16 + lc8) * 2));
#pragma unroll
            for (int mf = 0; mf < 2; mf++) {
                mma_f16(oc[mf][tt * 2][0], oc[mf][tt * 2][1], oc[mf][tt * 2][2], oc[mf][tt * 2][3],
                        pa[mf][kf][0], pa[mf][kf][1], pa[mf][kf][2], pa[mf][kf][3], b0, b1);
                mma_f16(oc[mf][tt * 2 + 1][0], oc[mf][tt * 2 + 1][1],
                        oc[mf][tt * 2 + 1][2], oc[mf][tt * 2 + 1][3],
                        pa[mf][kf][0], pa[mf][kf][1], pa[mf][kf][2], pa[mf][kf][3], b2, b3);
            }
        }
    }

    // ---- store O into the dead x-tile buffer ----
#pragma unroll
    for (int mf = 0; mf < 2; mf++) {
        int r = mi * 32 + mf * 16 + lq;
#pragma unroll
        for (int ni = 0; ni < 4; ni++) {
            int cb = hn * 32 + ni * 8 + kb2;
            *(uint32_t*)(As + r * AHS + cb) = pack_h2(oc[mf][ni][0], oc[mf][ni][1]);
            *(uint32_t*)(As + (r + 8) * AHS + cb) = pack_h2(oc[mf][ni][2], oc[mf][ni][3]);
        }
    }

    // ---- projection: out = O @ Wp^T + bp (chunk 0 in flight since before attention;
    //      run_gemm's entry sync orders all O stores before A reads) ----
    run_gemm(Wh + 196608, true, acc);              // Wp
#pragma unroll
    for (int mf = 0; mf < 2; mf++) {
        int r = mi * 32 + mf * 16 + lq;
        long gr0 = base + (r >> 3) * 128 + (r & 7);
        long gr1 = base + ((r + 8) >> 3) * 128 + ((r + 8) & 7);
#pragma unroll
        for (int ni = 0; ni < 4; ni++) {
            int cb = hn * 32 + ni * 8 + kb2;
            float b0 = __ldg(bp + cb), b1 = __ldg(bp + cb + 1);
            *(float2*)(out + gr0 * 256 + cb) =
                make_float2(acc[mf][ni][0] + b0, acc[mf][ni][1] + b1);
            *(float2*)(out + gr1 * 256 + cb) =
                make_float2(acc[mf][ni][2] + b0, acc[mf][ni][3] + b1);
        }
    }
}

// ---------------------------------------------------------------------------
// Launch
// ---------------------------------------------------------------------------
extern "C" void kernel_launch(void* const* d_in, const int* in_sizes, int n_in,
                              void* d_out, int out_size) {
    const float* x  = (const float*)d_in[0];
    const float* Wq = (const float*)d_in[1];
    const float* bq = (const float*)d_in[2];
    const float* Wk = (const float*)d_in[3];
    const float* bk = (const float*)d_in[4];
    const float* Wv = (const float*)d_in[5];
    const float* bv = (const float*)d_in[6];
    const float* Wp = (const float*)d_in[7];
    const float* bp = (const float*)d_in[8];
    float* out = (float*)d_out;

    __half* Wh;
    cudaGetSymbolAddress((void**)&Wh, g_Wh);

    cudaFuncSetAttribute((const void*)fused_kernel,
                         cudaFuncAttributeMaxDynamicSharedMemorySize, SMEM_BYTES);

    w2h_kernel<<<256, 256>>>(Wq, Wk, Wv, Wp);          // also builds transposed Wq/Wk
    prep_kernel<<<64, 256>>>(bq, bk, bv);              // coalesced via g_Wt

    fused_kernel<<<2048, 512, SMEM_BYTES>>>(x, Wh, bp, out);
}

// round 14
// speedup vs baseline: 1.0620x; 1.0620x over previous
#include <cuda_runtime.h>
#include <cuda_fp16.h>
#include <cstdint>

// Fixed shapes: B=8, H=W=128, C=256, heads=8, hd=32, ws=8
#define NTOK  131072

// device-global scratch (allocation-free rule)
__device__ __half g_Wh[4 * 256 * 256];        // fp16 weights: q,k,v,p
__device__ float  g_Wt[2][256][256];          // fp32 transposed Wq, Wk (k-major) for prep
__device__ __half g_tabh[3][64][256];         // fp16: pe@Wq^T+bq, pe@Wk^T+bk, bv

// ---------------------------------------------------------------------------
// helpers
// ---------------------------------------------------------------------------
__device__ __forceinline__ void mma_f16(float& c0, float& c1, float& c2, float& c3,
                                        uint32_t a0, uint32_t a1, uint32_t a2, uint32_t a3,
                                        uint32_t b0, uint32_t b1) {
    asm volatile(
        "mma.sync.aligned.m16n8k16.row.col.f32.f16.f16.f32 "
        "{%0,%1,%2,%3}, {%4,%5,%6,%7}, {%8,%9}, {%0,%1,%2,%3};\n"
        : "+f"(c0), "+f"(c1), "+f"(c2), "+f"(c3)
        : "r"(a0), "r"(a1), "r"(a2), "r"(a3), "r"(b0), "r"(b1));
}

__device__ __forceinline__ void ldsm4(uint32_t& r0, uint32_t& r1, uint32_t& r2, uint32_t& r3,
                                      uint32_t addr) {
    asm volatile("ldmatrix.sync.aligned.m8n8.x4.shared.b16 {%0,%1,%2,%3}, [%4];"
                 : "=r"(r0), "=r"(r1), "=r"(r2), "=r"(r3) : "r"(addr));
}

__device__ __forceinline__ void ldsm4t(uint32_t& r0, uint32_t& r1, uint32_t& r2, uint32_t& r3,
                                       uint32_t addr) {
    asm volatile("ldmatrix.sync.aligned.m8n8.x4.trans.shared.b16 {%0,%1,%2,%3}, [%4];"
                 : "=r"(r0), "=r"(r1), "=r"(r2), "=r"(r3) : "r"(addr));
}

__device__ __forceinline__ uint32_t smem_u32(const void* p) {
    uint32_t a;
    asm("{ .reg .u64 t; cvta.to.shared.u64 t, %1; cvt.u32.u64 %0, t; }" : "=r"(a) : "l"(p));
    return a;
}

__device__ __forceinline__ uint32_t pack_h2(float lo, float hi) {
    __half2 h = __floats2half2_rn(lo, hi);
    return *(uint32_t*)&h;
}

__device__ __forceinline__ void cp16(uint32_t smem, const void* gmem) {
    asm volatile("cp.async.cg.shared.global [%0], [%1], 16;" :: "r"(smem), "l"(gmem));
}

// ---------------------------------------------------------------------------
// w2h: fp32 -> fp16 weights [q,k,v,p]; also fp32 transposed Wq/Wk for prep
// ---------------------------------------------------------------------------
__global__ void w2h_kernel(const float* __restrict__ Wq, const float* __restrict__ Wk,
                           const float* __restrict__ Wv, const float* __restrict__ Wp) {
    int gid = blockIdx.x * 256 + threadIdx.x;       // 0..65535
    int mat = gid >> 14;
    int off = (gid & 16383) << 2;
    const float* W = (mat == 0) ? Wq : (mat == 1) ? Wk : (mat == 2) ? Wv : Wp;
    float4 v = *(const float4*)(W + off);
    __half2 h0 = __floats2half2_rn(v.x, v.y);
    __half2 h1 = __floats2half2_rn(v.z, v.w);
    *(uint2*)(g_Wh + (size_t)mat * 65536 + off) = make_uint2(*(uint32_t*)&h0, *(uint32_t*)&h1);
    if (mat < 2) {                                  // transpose for prep (k-major)
        int r = off >> 8;                           // output-channel row n
        int c = off & 255;                          // k column
        g_Wt[mat][c + 0][r] = v.x;
        g_Wt[mat][c + 1][r] = v.y;
        g_Wt[mat][c + 2][r] = v.z;
        g_Wt[mat][c + 3][r] = v.w;
    }
}

// ---------------------------------------------------------------------------
// prep: g_tabh[0] = pe@Wq^T+bq, [1] = pe@Wk^T+bk, [2] = bv  (fp16)
// Reads transposed weights -> coalesced (thread = n, loop = k).
// ---------------------------------------------------------------------------
__global__ void prep_kernel(const float* __restrict__ bq, const float* __restrict__ bk,
                            const float* __restrict__ bv) {
    __shared__ float per[256];
    int p = blockIdx.x, n = threadIdx.x;
    int wy = p >> 3, wx = p & 7;
    {
        int f = n & 63, quad = n >> 6;
        float coord = (quad < 2) ? (float)wx : (float)wy;
        float arg = 3.14f * coord * (float)f * (1.0f / 200.0f);
        per[n] = (quad & 1) ? cosf(arg) : sinf(arg);
    }
    __syncthreads();
    float sq = bq[n], sk = bk[n];
#pragma unroll 8
    for (int k = 0; k < 256; k++) {
        float pv = per[k];
        sq = fmaf(pv, g_Wt[0][k][n], sq);
        sk = fmaf(pv, g_Wt[1][k][n], sk);
    }
    g_tabh[0][p][n] = __float2half_rn(sq);
    g_tabh[1][p][n] = __float2half_rn(sk);
    g_tabh[2][p][n] = __float2half_rn(bv[n]);
}

// ---------------------------------------------------------------------------
// Fused kernel: one block per window (64 tokens), 512 threads / 16 warps.
// warp = (mi = warp&1 -> 32 query rows, hn = warp>>1 -> head / 32-col slice).
// Phases: stage x -> GEMM K -> GEMM V -> GEMM Q (regs) -> attention -> O to
// smem -> GEMM proj -> out.  Weights stream via cp.async (L2-resident).
// ---------------------------------------------------------------------------
#define AHS 264                   // halves; row stride of As/Ks/Vs
#define BHS 72                    // halves; weight-chunk row stride
#define OFF_K  33792u             // 64*264*2
#define OFF_V  67584u
#define OFF_B  101376u            // + 64*264*2
#define SMEM_BYTES 175104u        // + 2*256*72*2

__global__ void __launch_bounds__(512, 1) fused_kernel(
        const float* __restrict__ x, const __half* __restrict__ Wh,
        const float* __restrict__ bp, float* __restrict__ out) {
    extern __shared__ char smc[];
    __half* As = (__half*)smc;            // x tile, later O tile
    uint32_t smb = smem_u32(smc);

    int tid = threadIdx.x, lane = tid & 31, warp = tid >> 5;
    int mi = warp & 1, hn = warp >> 1;
    int lr = lane & 15, lc8 = (lane >> 4) << 3;
    int lq = lane >> 2, kb2 = (lane & 3) << 1;

    int win = blockIdx.x;
    int bi = win >> 8, wl = win & 255;
    int wyi = wl >> 4, wxi = wl & 15;
    long base = (long)bi * 16384 + (wyi * 8) * 128 + wxi * 8;   // + (t>>3)*128 + (t&7)

    // ---- stage x window tile (64 x 256 fp32 -> fp16 smem) ----
#pragma unroll
    for (int i = 0; i < 8; i++) {
        int f = tid + i * 512;            // 0..4095
        int t = f >> 6;
        int c4 = (f & 63) << 2;
        long gr = base + (t >> 3) * 128 + (t & 7);
        float4 v = *(const float4*)(x + gr * 256 + c4);
        __half2 h0 = __floats2half2_rn(v.x, v.y);
        __half2 h1 = __floats2half2_rn(v.z, v.w);
        *(uint2*)(As + t * AHS + c4) = make_uint2(*(uint32_t*)&h0, *(uint32_t*)&h1);
    }

    // ---- shared GEMM mainloop: acc[mf][ni] = A[rows mi*32..] @ Wm[cols hn*32..]^T
    auto run_gemm = [&](const __half* Wm, float (&acc)[2][4][4]) {
#pragma unroll
        for (int a = 0; a < 2; a++)
#pragma unroll
            for (int b = 0; b < 4; b++)
#pragma unroll
                for (int r = 0; r < 4; r++) acc[a][b][r] = 0.f;
        // issue chunk 0 (256 rows x 64 halves = 8 x 16B segs per row)
#pragma unroll
        for (int i = 0; i < 4; i++) {
            int f = tid + i * 512;        // 0..2047
            int row = f >> 3, seg = f & 7;
            cp16(smb + OFF_B + (uint32_t)(row * BHS + seg * 8) * 2,
                 Wm + (size_t)row * 256 + seg * 8);
        }
        asm volatile("cp.async.commit_group;");
        asm volatile("cp.async.wait_group 0;");
        __syncthreads();

        for (int c = 0; c < 4; c++) {
            int buf = c & 1;
            if (c < 3) {
                int k0 = (c + 1) * 64;
#pragma unroll
                for (int i = 0; i < 4; i++) {
                    int f = tid + i * 512;
                    int row = f >> 3, seg = f & 7;
                    cp16(smb + OFF_B +
                         (uint32_t)((buf ^ 1) * 256 * BHS + row * BHS + seg * 8) * 2,
                         Wm + (size_t)row * 256 + k0 + seg * 8);
                }
                asm volatile("cp.async.commit_group;");
            }
            uint32_t bB = smb + OFF_B + (uint32_t)buf * (256 * BHS * 2);
#pragma unroll
            for (int kt = 0; kt < 4; kt++) {
                int kcol = c * 64 + kt * 16 + lc8;
                uint32_t af[2][4];
#pragma unroll
                for (int mf = 0; mf < 2; mf++)
                    ldsm4(af[mf][0], af[mf][1], af[mf][2], af[mf][3],
                          smb + (uint32_t)(((mi * 32 + mf * 16 + lr) * AHS + kcol) * 2));
                uint32_t bf[4][2];
#pragma unroll
                for (int ntp = 0; ntp < 2; ntp++) {
                    uint32_t r0, r1, r2, r3;
                    ldsm4(r0, r1, r2, r3,
                          bB + (uint32_t)(((hn * 32 + ntp * 16 + lr) * BHS + kt * 16 + lc8) * 2));
                    bf[ntp * 2][0] = r0; bf[ntp * 2][1] = r2;
                    bf[ntp * 2 + 1][0] = r1; bf[ntp * 2 + 1][1] = r3;
                }
#pragma unroll
                for (int mf = 0; mf < 2; mf++)
#pragma unroll
                    for (int ni = 0; ni < 4; ni++)
                        mma_f16(acc[mf][ni][0], acc[mf][ni][1], acc[mf][ni][2], acc[mf][ni][3],
                                af[mf][0], af[mf][1], af[mf][2], af[mf][3],
                                bf[ni][0], bf[ni][1]);
            }
            if (c < 3) asm volatile("cp.async.wait_group 0;");
            __syncthreads();
        }
    };

    // C-frag + fp16 table -> smem (used for K and V)
    auto store_kv = [&](float (&acc)[2][4][4], const __half* tab, uint32_t dstOff) {
#pragma unroll
        for (int mf = 0; mf < 2; mf++) {
            int r = mi * 32 + mf * 16 + lq;
#pragma unroll
            for (int ni = 0; ni < 4; ni++) {
                int cb = hn * 32 + ni * 8 + kb2;
                float2 t0 = __half22float2(*(const __half2*)&tab[r * 256 + cb]);
                float2 t1 = __half22float2(*(const __half2*)&tab[(r + 8) * 256 + cb]);
                *(uint32_t*)(smc + dstOff + (uint32_t)((r * AHS + cb) * 2)) =
                    pack_h2(acc[mf][ni][0] + t0.x, acc[mf][ni][1] + t0.y);
                *(uint32_t*)(smc + dstOff + (uint32_t)(((r + 8) * AHS + cb) * 2)) =
                    pack_h2(acc[mf][ni][2] + t1.x, acc[mf][ni][3] + t1.y);
            }
        }
    };

    float acc[2][4][4];

    // ---- K, V ----
    run_gemm(Wh + 65536, acc);                     // Wk
    store_kv(acc, &g_tabh[1][0][0], OFF_K);
    run_gemm(Wh + 131072, acc);                    // Wv
    store_kv(acc, &g_tabh[2][0][0], OFF_V);

    // ---- Q (stays in registers as mma A-frags, scale folded) ----
    run_gemm(Wh, acc);                             // Wq
    uint32_t afQ[2][2][4];
    {
        const __half* tq = &g_tabh[0][0][0];
        const float s = 0.17677669529663687f;      // 1/sqrt(32)
#pragma unroll
        for (int mf = 0; mf < 2; mf++) {
            int r = mi * 32 + mf * 16 + lq;
#pragma unroll
            for (int kf = 0; kf < 2; kf++) {
#pragma unroll
                for (int h = 0; h < 2; h++) {
                    int ni = 2 * kf + h;
                    int cb = hn * 32 + ni * 8 + kb2;
                    float2 t0 = __half22float2(*(const __half2*)&tq[r * 256 + cb]);
                    float2 t1 = __half22float2(*(const __half2*)&tq[(r + 8) * 256 + cb]);
                    afQ[mf][kf][2 * h] =
                        pack_h2((acc[mf][ni][0] + t0.x) * s, (acc[mf][ni][1] + t0.y) * s);
                    afQ[mf][kf][2 * h + 1] =
                        pack_h2((acc[mf][ni][2] + t1.x) * s, (acc[mf][ni][3] + t1.y) * s);
                }
            }
        }
    }

    // ---- S = Q K^T (32 rows x 64 keys per warp) ----
    float sc[2][8][4];
#pragma unroll
    for (int mf = 0; mf < 2; mf++)
#pragma unroll
        for (int nf = 0; nf < 8; nf++)
#pragma unroll
            for (int r = 0; r < 4; r++) sc[mf][nf][r] = 0.f;

#pragma unroll
    for (int kt = 0; kt < 2; kt++) {
#pragma unroll
        for (int nt = 0; nt < 4; nt++) {
            uint32_t b0, b1, b2, b3;
            ldsm4(b0, b1, b2, b3,
                  smb + OFF_K + (uint32_t)(((nt * 16 + lr) * AHS + hn * 32 + kt * 16 + lc8) * 2));
#pragma unroll
            for (int mf = 0; mf < 2; mf++) {
                mma_f16(sc[mf][nt * 2][0], sc[mf][nt * 2][1], sc[mf][nt * 2][2], sc[mf][nt * 2][3],
                        afQ[mf][kt][0], afQ[mf][kt][1], afQ[mf][kt][2], afQ[mf][kt][3], b0, b2);
                mma_f16(sc[mf][nt * 2 + 1][0], sc[mf][nt * 2 + 1][1],
                        sc[mf][nt * 2 + 1][2], sc[mf][nt * 2 + 1][3],
                        afQ[mf][kt][0], afQ[mf][kt][1], afQ[mf][kt][2], afQ[mf][kt][3], b1, b3);
            }
        }
    }

    // ---- softmax + P pack (scale already folded into Q) ----
    uint32_t pa[2][4][4];
#pragma unroll
    for (int mf = 0; mf < 2; mf++) {
        float m0 = -1e30f, m1 = -1e30f;
#pragma unroll
        for (int nf = 0; nf < 8; nf++) {
            m0 = fmaxf(m0, fmaxf(sc[mf][nf][0], sc[mf][nf][1]));
            m1 = fmaxf(m1, fmaxf(sc[mf][nf][2], sc[mf][nf][3]));
        }
        m0 = fmaxf(m0, __shfl_xor_sync(0xffffffffu, m0, 1));
        m0 = fmaxf(m0, __shfl_xor_sync(0xffffffffu, m0, 2));
        m1 = fmaxf(m1, __shfl_xor_sync(0xffffffffu, m1, 1));
        m1 = fmaxf(m1, __shfl_xor_sync(0xffffffffu, m1, 2));
        float s0 = 0.f, s1 = 0.f;
#pragma unroll
        for (int nf = 0; nf < 8; nf++) {
            sc[mf][nf][0] = __expf(sc[mf][nf][0] - m0);
            sc[mf][nf][1] = __expf(sc[mf][nf][1] - m0);
            sc[mf][nf][2] = __expf(sc[mf][nf][2] - m1);
            sc[mf][nf][3] = __expf(sc[mf][nf][3] - m1);
            s0 += sc[mf][nf][0] + sc[mf][nf][1];
            s1 += sc[mf][nf][2] + sc[mf][nf][3];
        }
        s0 += __shfl_xor_sync(0xffffffffu, s0, 1);
        s0 += __shfl_xor_sync(0xffffffffu, s0, 2);
        s1 += __shfl_xor_sync(0xffffffffu, s1, 1);
        s1 += __shfl_xor_sync(0xffffffffu, s1, 2);
        float inv0 = 1.0f / s0, inv1 = 1.0f / s1;
#pragma unroll
        for (int kf = 0; kf < 4; kf++) {
            pa[mf][kf][0] = pack_h2(sc[mf][2 * kf][0] * inv0, sc[mf][2 * kf][1] * inv0);
            pa[mf][kf][1] = pack_h2(sc[mf][2 * kf][2] * inv1, sc[mf][2 * kf][3] * inv1);
            pa[mf][kf][2] = pack_h2(sc[mf][2 * kf + 1][0] * inv0, sc[mf][2 * kf + 1][1] * inv0);
            pa[mf][kf][3] = pack_h2(sc[mf][2 * kf + 1][2] * inv1, sc[mf][2 * kf + 1][3] * inv1);
        }
    }

    // ---- O = P V ----
    float oc[2][4][4];
#pragma unroll
    for (int mf = 0; mf < 2; mf++)
#pragma unroll
        for (int nf = 0; nf < 4; nf++)
#pragma unroll
            for (int r = 0; r < 4; r++) oc[mf][nf][r] = 0.f;

#pragma unroll
    for (int kf = 0; kf < 4; kf++) {
#pragma unroll
        for (int tt = 0; tt < 2; tt++) {
            uint32_t b0, b1, b2, b3;
            ldsm4t(b0, b1, b2, b3,
                   smb + OFF_V + (uint32_t)(((kf * 16 + lr) * AHS + hn * 32 + tt * 16 + lc8) * 2));
#pragma unroll
            for (int mf = 0; mf < 2; mf++) {
                mma_f16(oc[mf][tt * 2][0], oc[mf][tt * 2][1], oc[mf][tt * 2][2], oc[mf][tt * 2][3],
                        pa[mf][kf][0], pa[mf][kf][1], pa[mf][kf][2], pa[mf][kf][3], b0, b1);
                mma_f16(oc[mf][tt * 2 + 1][0], oc[mf][tt * 2 + 1][1],
                        oc[mf][tt * 2 + 1][2], oc[mf][tt * 2 + 1][3],
                        pa[mf][kf][0], pa[mf][kf][1], pa[mf][kf][2], pa[mf][kf][3], b2, b3);
            }
        }
    }

    // ---- store O into the dead x-tile buffer ----
#pragma unroll
    for (int mf = 0; mf < 2; mf++) {
        int r = mi * 32 + mf * 16 + lq;
#pragma unroll
        for (int ni = 0; ni < 4; ni++) {
            int cb = hn * 32 + ni * 8 + kb2;
            *(uint32_t*)(As + r * AHS + cb) = pack_h2(oc[mf][ni][0], oc[mf][ni][1]);
            *(uint32_t*)(As + (r + 8) * AHS + cb) = pack_h2(oc[mf][ni][2], oc[mf][ni][3]);
        }
    }

    // ---- projection: out = O @ Wp^T + bp (barrier inside run_gemm orders O stores) ----
    run_gemm(Wh + 196608, acc);                    // Wp
#pragma unroll
    for (int mf = 0; mf < 2; mf++) {
        int r = mi * 32 + mf * 16 + lq;
        long gr0 = base + (r >> 3) * 128 + (r & 7);
        long gr1 = base + ((r + 8) >> 3) * 128 + ((r + 8) & 7);
#pragma unroll
        for (int ni = 0; ni < 4; ni++) {
            int cb = hn * 32 + ni * 8 + kb2;
            float b0 = __ldg(bp + cb), b1 = __ldg(bp + cb + 1);
            *(float2*)(out + gr0 * 256 + cb) =
                make_float2(acc[mf][ni][0] + b0, acc[mf][ni][1] + b1);
            *(float2*)(out + gr1 * 256 + cb) =
                make_float2(acc[mf][ni][2] + b0, acc[mf][ni][3] + b1);
        }
    }
}

// ---------------------------------------------------------------------------
// Launch
// ---------------------------------------------------------------------------
extern "C" void kernel_launch(void* const* d_in, const int* in_sizes, int n_in,
                              void* d_out, int out_size) {
    const float* x  = (const float*)d_in[0];
    const float* Wq = (const float*)d_in[1];
    const float* bq = (const float*)d_in[2];
    const float* Wk = (const float*)d_in[3];
    const float* bk = (const float*)d_in[4];
    const float* Wv = (const float*)d_in[5];
    const float* bv = (const float*)d_in[6];
    const float* Wp = (const float*)d_in[7];
    const float* bp = (const float*)d_in[8];
    float* out = (float*)d_out;

    __half* Wh;
    cudaGetSymbolAddress((void**)&Wh, g_Wh);

    cudaFuncSetAttribute((const void*)fused_kernel,
                         cudaFuncAttributeMaxDynamicSharedMemorySize, SMEM_BYTES);

    w2h_kernel<<<256, 256>>>(Wq, Wk, Wv, Wp);          // also builds transposed Wq/Wk
    prep_kernel<<<64, 256>>>(bq, bk, bv);              // coalesced via g_Wt

    fused_kernel<<<2048, 512, SMEM_BYTES>>>(x, Wh, bp, out);
}